// round 9
// baseline (speedup 1.0000x reference)
#include <cuda_runtime.h>
#include <cuda_fp16.h>

#define N_NODES 100000
#define N_EDGES 1600000
#define D 64
#define SCAN_NB 391   // 391*256 = 100096 >= N_NODES

typedef unsigned long long ull;

// Scratch (static __device__ — allocation-free per harness rules)
__device__ int     g_is64;
__device__ int     g_deg[N_NODES];
__device__ int     g_rowoff[N_NODES + 1];
__device__ int     g_cursor[N_NODES];
__device__ float   g_dinv[N_NODES];
__device__ int     g_srcidx[N_EDGES];
__device__ int     g_bsum[512];
__device__ float   g_A[N_NODES * D];        // aggregated (mean) neighbor feats, fp32
__device__ float   g_H[N_NODES * D];        // layer-1 hidden, fp32
__device__ __half2 g_Xh[N_NODES * D / 2];   // fp16 copy of x (gather source, L1)
__device__ __half2 g_Hh[N_NODES * D / 2];   // fp16 copy of H (gather source, L2)

// ---------- packed f32x2 helpers ----------
__device__ __forceinline__ ull fma2(ull a, ull b, ull c) {
    ull d;
    asm("fma.rn.f32x2 %0, %1, %2, %3;" : "=l"(d) : "l"(a), "l"(b), "l"(c));
    return d;
}
__device__ __forceinline__ ull pack2(float x, float y) {
    ull d;
    asm("mov.b64 %0, {%1, %2};" : "=l"(d) : "f"(x), "f"(y));
    return d;
}
__device__ __forceinline__ void unpack2(ull v, float& x, float& y) {
    asm("mov.b64 {%0, %1}, %2;" : "=f"(x), "=f"(y) : "l"(v));
}

__device__ __forceinline__ int clampN(int v) {
    return min(max(v, 0), N_NODES - 1);
}
__device__ __forceinline__ int load_id(const void* ei, long long idx, int is64) {
    int v = is64 ? (int)((const long long*)ei)[idx] : ((const int*)ei)[idx];
    return clampN(v);
}

// ---------- init: zero degrees + dtype detect ----------
__global__ void k_init(const int* __restrict__ ei32) {
    int i = blockIdx.x * blockDim.x + threadIdx.x;
    if (i < N_NODES) g_deg[i] = 0;
    if (i == 0) {
        int odd_zero = 1;
#pragma unroll
        for (int j = 1; j < 64; j += 2)
            if (ei32[j] != 0) odd_zero = 0;
        g_is64 = odd_zero;
    }
}

// ---------- x -> fp16 copy ----------
__global__ void k_convert(const float* __restrict__ x) {
    int i = blockIdx.x * blockDim.x + threadIdx.x;   // one float4 -> two half2
    if (i < N_NODES * D / 4) {
        float4 v = ((const float4*)x)[i];
        g_Xh[2 * i]     = __float22half2_rn(make_float2(v.x, v.y));
        g_Xh[2 * i + 1] = __float22half2_rn(make_float2(v.z, v.w));
    }
}

__global__ void k_hist(const void* __restrict__ ei) {
    int e = blockIdx.x * blockDim.x + threadIdx.x;
    if (e < N_EDGES) {
        int is64 = g_is64;
        int dst = load_id(ei, (long long)N_EDGES + e, is64);
        atomicAdd(&g_deg[dst], 1);
    }
}

__global__ void k_scan1() {
    __shared__ int sh[256];
    int i = blockIdx.x * 256 + threadIdx.x;
    int t = threadIdx.x;
    sh[t] = (i < N_NODES) ? g_deg[i] : 0;
    __syncthreads();
    for (int off = 128; off > 0; off >>= 1) {
        if (t < off) sh[t] += sh[t + off];
        __syncthreads();
    }
    if (t == 0) g_bsum[blockIdx.x] = sh[0];
}

// per-block: redundant scan of 391 block sums + local scan + write CSR arrays
__global__ void k_scan23() {
    __shared__ int sb2[512];
    __shared__ int sh[256];
    int b = blockIdx.x;
    int t = threadIdx.x;
    sb2[t]       = (t < SCAN_NB) ? g_bsum[t] : 0;
    sb2[t + 256] = (t + 256 < SCAN_NB) ? g_bsum[t + 256] : 0;
    __syncthreads();
    for (int off = 1; off < 512; off <<= 1) {
        int v0 = (t >= off) ? sb2[t - off] : 0;
        int v1 = (t + 256 >= off) ? sb2[t + 256 - off] : 0;
        __syncthreads();
        sb2[t] += v0;
        sb2[t + 256] += v1;
        __syncthreads();
    }
    int boff = (b == 0) ? 0 : sb2[b - 1];
    int i = b * 256 + t;
    int d = (i < N_NODES) ? g_deg[i] : 0;
    sh[t] = d;
    __syncthreads();
    for (int off = 1; off < 256; off <<= 1) {
        int v = (t >= off) ? sh[t - off] : 0;
        __syncthreads();
        sh[t] += v;
        __syncthreads();
    }
    if (i < N_NODES) {
        int excl = sh[t] - d + boff;
        g_rowoff[i] = excl;
        g_cursor[i] = excl;
        g_dinv[i] = 1.0f / (float)max(d, 1);
    }
    if (i == 0) g_rowoff[N_NODES] = N_EDGES;
}

__global__ void k_fill(const void* __restrict__ ei) {
    int e = blockIdx.x * blockDim.x + threadIdx.x;
    if (e < N_EDGES) {
        int is64 = g_is64;
        int dst = load_id(ei, (long long)N_EDGES + e, is64);
        int src = load_id(ei, e, is64);
        int pos = atomicAdd(&g_cursor[dst], 1);
        pos = min(max(pos, 0), N_EDGES - 1);
        g_srcidx[pos] = src;
    }
}

// ---------- mean aggregation: warp per node, fp16 gather, fp32 accumulate ----------
template <bool FIRST>
__global__ void k_agg() {
    const __half2* __restrict__ feat = FIRST ? g_Xh : g_Hh;
    int gw = (blockIdx.x * blockDim.x + threadIdx.x) >> 5;
    int lane = threadIdx.x & 31;
    if (gw >= N_NODES) return;
    int s = g_rowoff[gw], e = g_rowoff[gw + 1];
    float ax = 0.f, ay = 0.f;
    int i = s;
    for (; i + 3 < e; i += 4) {   // 4 gathers in flight
        int s0 = g_srcidx[i], s1 = g_srcidx[i + 1];
        int s2 = g_srcidx[i + 2], s3 = g_srcidx[i + 3];
        float2 v0 = __half22float2(feat[s0 * 32 + lane]);
        float2 v1 = __half22float2(feat[s1 * 32 + lane]);
        float2 v2 = __half22float2(feat[s2 * 32 + lane]);
        float2 v3 = __half22float2(feat[s3 * 32 + lane]);
        ax += v0.x + v1.x + v2.x + v3.x;
        ay += v0.y + v1.y + v2.y + v3.y;
    }
    for (; i < e; i++) {
        int s0 = g_srcidx[i];
        float2 v = __half22float2(feat[s0 * 32 + lane]);
        ax += v.x; ay += v.y;
    }
    float di = g_dinv[gw];
    *(float2*)&g_A[gw * D + lane * 2] = make_float2(ax * di, ay * di);
}

// ---------- fused dual-linear: out = A@Wl^T + b + X@Wr^T (+relu) ----------
// 128 threads/block, 2 nodes/thread, packed FFMA2, LDS.128 weight loads,
// one-iteration double-buffered prefetch. Layer-1 also emits fp16 H (full 64).
template <bool FIRST>
__global__ void __launch_bounds__(128)
k_dense(const float* __restrict__ xext,
        const float* __restrict__ Wl, const float* __restrict__ bias,
        const float* __restrict__ Wr, float* __restrict__ outext) {
    __shared__ float sWl[64 * 64];
    __shared__ float sWr[64 * 64];
    __shared__ float sb[64];
    const float* __restrict__ X = FIRST ? xext : (const float*)g_H;
    float* out = FIRST ? (float*)g_H : outext;
    int tid = threadIdx.x;
    for (int i = tid; i < 4096; i += 128) {
        int j = i >> 6, k = i & 63;
        sWl[k * 64 + j] = Wl[i];   // sW[k][j] = W[j][k]
        sWr[k * 64 + j] = Wr[i];
    }
    if (tid < 64) sb[tid] = bias[tid];
    __syncthreads();

    int n0 = blockIdx.x * 256 + tid;
    int n1 = n0 + 128;
    bool v0 = n0 < N_NODES, v1 = n1 < N_NODES;
    int m0 = v0 ? n0 : 0, m1 = v1 ? n1 : 0;

    ull acc0[32], acc1[32];
#pragma unroll
    for (int j = 0; j < 32; j++) {
        ull bb = pack2(sb[2 * j], sb[2 * j + 1]);
        acc0[j] = bb; acc1[j] = bb;
    }
    const float4* A0 = (const float4*)(g_A + m0 * D);
    const float4* A1 = (const float4*)(g_A + m1 * D);
    const float4* X0 = (const float4*)(X + m0 * D);
    const float4* X1 = (const float4*)(X + m1 * D);

    float4 a0 = A0[0], xq0 = X0[0], a1 = A1[0], xq1 = X1[0];

#pragma unroll 1
    for (int kq = 0; kq < 16; kq++) {
        float4 na0, nx0, na1, nx1;
        if (kq < 15) {
            na0 = A0[kq + 1]; nx0 = X0[kq + 1];
            na1 = A1[kq + 1]; nx1 = X1[kq + 1];
        }
        float fa0[4] = {a0.x, a0.y, a0.z, a0.w};
        float fx0[4] = {xq0.x, xq0.y, xq0.z, xq0.w};
        float fa1[4] = {a1.x, a1.y, a1.z, a1.w};
        float fx1[4] = {xq1.x, xq1.y, xq1.z, xq1.w};
#pragma unroll
        for (int kk = 0; kk < 4; kk++) {
            int k = kq * 4 + kk;
            ull pa0 = pack2(fa0[kk], fa0[kk]);
            ull px0 = pack2(fx0[kk], fx0[kk]);
            ull pa1 = pack2(fa1[kk], fa1[kk]);
            ull px1 = pack2(fx1[kk], fx1[kk]);
            const ulonglong2* wlp = (const ulonglong2*)&sWl[k * 64];
            const ulonglong2* wrp = (const ulonglong2*)&sWr[k * 64];
#pragma unroll
            for (int jp = 0; jp < 16; jp++) {
                ulonglong2 wl = wlp[jp];   // LDS.128 broadcast
                ulonglong2 wr = wrp[jp];
                acc0[2 * jp]     = fma2(wl.x, pa0, fma2(wr.x, px0, acc0[2 * jp]));
                acc0[2 * jp + 1] = fma2(wl.y, pa0, fma2(wr.y, px0, acc0[2 * jp + 1]));
                acc1[2 * jp]     = fma2(wl.x, pa1, fma2(wr.x, px1, acc1[2 * jp]));
                acc1[2 * jp + 1] = fma2(wl.y, pa1, fma2(wr.y, px1, acc1[2 * jp + 1]));
            }
        }
        a0 = na0; xq0 = nx0; a1 = na1; xq1 = nx1;
    }

#pragma unroll
    for (int half = 0; half < 2; half++) {
        bool valid = half ? v1 : v0;
        if (!valid) continue;
        int node = half ? n1 : n0;
        ull* acc = half ? acc1 : acc0;
        float4* o = (float4*)(out + node * D);
        unsigned hb[32];   // 64 halves = 32 half2 words = 8 uint4
#pragma unroll
        for (int q = 0; q < 16; q++) {
            float r0, r1, r2, r3;
            unpack2(acc[2 * q], r0, r1);
            unpack2(acc[2 * q + 1], r2, r3);
            if (FIRST) {
                r0 = fmaxf(r0, 0.f); r1 = fmaxf(r1, 0.f);
                r2 = fmaxf(r2, 0.f); r3 = fmaxf(r3, 0.f);
                __half2 h01 = __float22half2_rn(make_float2(r0, r1));
                __half2 h23 = __float22half2_rn(make_float2(r2, r3));
                hb[2 * q]     = *(unsigned*)&h01;
                hb[2 * q + 1] = *(unsigned*)&h23;
            }
            o[q] = make_float4(r0, r1, r2, r3);
        }
        if (FIRST) {
            uint4* hd = (uint4*)(g_Hh + node * 32);
            const uint4* hs = (const uint4*)hb;
#pragma unroll
            for (int q = 0; q < 8; q++) hd[q] = hs[q];
        }
    }
}

extern "C" void kernel_launch(void* const* d_in, const int* in_sizes, int n_in,
                              void* d_out, int out_size) {
    const float* x   = (const float*)d_in[0];
    const void*  ei  = d_in[1];
    const float* W1l = (const float*)d_in[2];
    const float* b1  = (const float*)d_in[3];
    const float* W1r = (const float*)d_in[4];
    const float* W2l = (const float*)d_in[5];
    const float* b2  = (const float*)d_in[6];
    const float* W2r = (const float*)d_in[7];
    float* out = (float*)d_out;

    k_init<<<SCAN_NB, 256>>>((const int*)ei);
    k_convert<<<(N_NODES * D / 4 + 255) / 256, 256>>>(x);
    k_hist<<<(N_EDGES + 255) / 256, 256>>>(ei);
    k_scan1<<<SCAN_NB, 256>>>();
    k_scan23<<<SCAN_NB, 256>>>();
    k_fill<<<(N_EDGES + 255) / 256, 256>>>(ei);

    const int DNB = (N_NODES + 255) / 256;   // 391 blocks of 128 threads

    // Layer 1
    k_agg<true><<<(N_NODES * 32 + 255) / 256, 256>>>();
    k_dense<true><<<DNB, 128>>>(x, W1l, b1, W1r, nullptr);

    // Layer 2
    k_agg<false><<<(N_NODES * 32 + 255) / 256, 256>>>();
    k_dense<false><<<DNB, 128>>>(x, W2l, b2, W2r, out);
}

// round 10
// speedup vs baseline: 1.4902x; 1.4902x over previous
#include <cuda_runtime.h>
#include <cuda_fp16.h>

#define N_NODES 100000
#define N_EDGES 1600000
#define D 64
#define SCAN_NB 391   // 391*256 = 100096 >= N_NODES

typedef unsigned long long ull;

// Scratch (static __device__ — allocation-free per harness rules)
__device__ int     g_is64;
__device__ int     g_deg[N_NODES];
__device__ int     g_rowoff[N_NODES + 1];
__device__ int     g_cursor[N_NODES];
__device__ float   g_dinv[N_NODES];
__device__ int     g_srcidx[N_EDGES];
__device__ int     g_bsum[512];
__device__ float   g_A[N_NODES * D];        // aggregated (mean) neighbor feats, fp32
__device__ float   g_H[N_NODES * D];        // layer-1 hidden, fp32
__device__ __half2 g_Xh[N_NODES * D / 2];   // fp16 copy of x (gather source, L1)
__device__ __half2 g_Hh[N_NODES * D / 2];   // fp16 copy of H (gather source, L2)

// ---------- packed f32x2 helpers ----------
__device__ __forceinline__ ull fma2(ull a, ull b, ull c) {
    ull d;
    asm("fma.rn.f32x2 %0, %1, %2, %3;" : "=l"(d) : "l"(a), "l"(b), "l"(c));
    return d;
}
__device__ __forceinline__ ull pack2(float x, float y) {
    ull d;
    asm("mov.b64 %0, {%1, %2};" : "=l"(d) : "f"(x), "f"(y));
    return d;
}
__device__ __forceinline__ void unpack2(ull v, float& x, float& y) {
    asm("mov.b64 {%0, %1}, %2;" : "=f"(x), "=f"(y) : "l"(v));
}

__device__ __forceinline__ int clampN(int v) {
    return min(max(v, 0), N_NODES - 1);
}
__device__ __forceinline__ int load_id(const void* ei, long long idx, int is64) {
    int v = is64 ? (int)((const long long*)ei)[idx] : ((const int*)ei)[idx];
    return clampN(v);
}

// ---------- init: zero degrees + dtype detect ----------
__global__ void k_init(const int* __restrict__ ei32) {
    int i = blockIdx.x * blockDim.x + threadIdx.x;
    if (i < N_NODES) g_deg[i] = 0;
    if (i == 0) {
        int odd_zero = 1;
#pragma unroll
        for (int j = 1; j < 64; j += 2)
            if (ei32[j] != 0) odd_zero = 0;
        g_is64 = odd_zero;
    }
}

// ---------- x -> fp16 copy ----------
__global__ void k_convert(const float* __restrict__ x) {
    int i = blockIdx.x * blockDim.x + threadIdx.x;   // one float4 -> two half2
    if (i < N_NODES * D / 4) {
        float4 v = ((const float4*)x)[i];
        g_Xh[2 * i]     = __float22half2_rn(make_float2(v.x, v.y));
        g_Xh[2 * i + 1] = __float22half2_rn(make_float2(v.z, v.w));
    }
}

// ---------- H -> fp16 copy (keeps k_dense register-lean) ----------
__global__ void k_convertH() {
    int i = blockIdx.x * blockDim.x + threadIdx.x;
    if (i < N_NODES * D / 4) {
        float4 v = ((const float4*)g_H)[i];
        g_Hh[2 * i]     = __float22half2_rn(make_float2(v.x, v.y));
        g_Hh[2 * i + 1] = __float22half2_rn(make_float2(v.z, v.w));
    }
}

__global__ void k_hist(const void* __restrict__ ei) {
    int e = blockIdx.x * blockDim.x + threadIdx.x;
    if (e < N_EDGES) {
        int is64 = g_is64;
        int dst = load_id(ei, (long long)N_EDGES + e, is64);
        atomicAdd(&g_deg[dst], 1);
    }
}

__global__ void k_scan1() {
    __shared__ int sh[256];
    int i = blockIdx.x * 256 + threadIdx.x;
    int t = threadIdx.x;
    sh[t] = (i < N_NODES) ? g_deg[i] : 0;
    __syncthreads();
    for (int off = 128; off > 0; off >>= 1) {
        if (t < off) sh[t] += sh[t + off];
        __syncthreads();
    }
    if (t == 0) g_bsum[blockIdx.x] = sh[0];
}

// per-block: redundant scan of 391 block sums + local scan + write CSR arrays
__global__ void k_scan23() {
    __shared__ int sb2[512];
    __shared__ int sh[256];
    int b = blockIdx.x;
    int t = threadIdx.x;
    sb2[t]       = (t < SCAN_NB) ? g_bsum[t] : 0;
    sb2[t + 256] = (t + 256 < SCAN_NB) ? g_bsum[t + 256] : 0;
    __syncthreads();
    for (int off = 1; off < 512; off <<= 1) {
        int v0 = (t >= off) ? sb2[t - off] : 0;
        int v1 = (t + 256 >= off) ? sb2[t + 256 - off] : 0;
        __syncthreads();
        sb2[t] += v0;
        sb2[t + 256] += v1;
        __syncthreads();
    }
    int boff = (b == 0) ? 0 : sb2[b - 1];
    int i = b * 256 + t;
    int d = (i < N_NODES) ? g_deg[i] : 0;
    sh[t] = d;
    __syncthreads();
    for (int off = 1; off < 256; off <<= 1) {
        int v = (t >= off) ? sh[t - off] : 0;
        __syncthreads();
        sh[t] += v;
        __syncthreads();
    }
    if (i < N_NODES) {
        int excl = sh[t] - d + boff;
        g_rowoff[i] = excl;
        g_cursor[i] = excl;
        g_dinv[i] = 1.0f / (float)max(d, 1);
    }
    if (i == 0) g_rowoff[N_NODES] = N_EDGES;
}

__global__ void k_fill(const void* __restrict__ ei) {
    int e = blockIdx.x * blockDim.x + threadIdx.x;
    if (e < N_EDGES) {
        int is64 = g_is64;
        int dst = load_id(ei, (long long)N_EDGES + e, is64);
        int src = load_id(ei, e, is64);
        int pos = atomicAdd(&g_cursor[dst], 1);
        pos = min(max(pos, 0), N_EDGES - 1);
        g_srcidx[pos] = src;
    }
}

// ---------- mean aggregation: warp per node, fp16 gather, fp32 accumulate ----------
template <bool FIRST>
__global__ void k_agg() {
    const __half2* __restrict__ feat = FIRST ? g_Xh : g_Hh;
    int gw = (blockIdx.x * blockDim.x + threadIdx.x) >> 5;
    int lane = threadIdx.x & 31;
    if (gw >= N_NODES) return;
    int s = g_rowoff[gw], e = g_rowoff[gw + 1];
    float ax = 0.f, ay = 0.f;
    int i = s;
    for (; i + 3 < e; i += 4) {   // 4 gathers in flight
        int s0 = g_srcidx[i], s1 = g_srcidx[i + 1];
        int s2 = g_srcidx[i + 2], s3 = g_srcidx[i + 3];
        float2 v0 = __half22float2(feat[s0 * 32 + lane]);
        float2 v1 = __half22float2(feat[s1 * 32 + lane]);
        float2 v2 = __half22float2(feat[s2 * 32 + lane]);
        float2 v3 = __half22float2(feat[s3 * 32 + lane]);
        ax += v0.x + v1.x + v2.x + v3.x;
        ay += v0.y + v1.y + v2.y + v3.y;
    }
    for (; i < e; i++) {
        int s0 = g_srcidx[i];
        float2 v = __half22float2(feat[s0 * 32 + lane]);
        ax += v.x; ay += v.y;
    }
    float di = g_dinv[gw];
    *(float2*)&g_A[gw * D + lane * 2] = make_float2(ax * di, ay * di);
}

// ---------- fused dual-linear: out = A@Wl^T + b + X@Wr^T (+relu) ----------
// 128 threads/block, 2 nodes/thread, packed FFMA2, LDS.128 weight loads,
// one-iteration double-buffered prefetch. (Register-lean epilogue: fp32 only.)
template <bool FIRST>
__global__ void __launch_bounds__(128)
k_dense(const float* __restrict__ xext,
        const float* __restrict__ Wl, const float* __restrict__ bias,
        const float* __restrict__ Wr, float* __restrict__ outext) {
    __shared__ float sWl[64 * 64];
    __shared__ float sWr[64 * 64];
    __shared__ float sb[64];
    const float* __restrict__ X = FIRST ? xext : (const float*)g_H;
    float* out = FIRST ? (float*)g_H : outext;
    int tid = threadIdx.x;
    for (int i = tid; i < 4096; i += 128) {
        int j = i >> 6, k = i & 63;
        sWl[k * 64 + j] = Wl[i];   // sW[k][j] = W[j][k]
        sWr[k * 64 + j] = Wr[i];
    }
    if (tid < 64) sb[tid] = bias[tid];
    __syncthreads();

    int n0 = blockIdx.x * 256 + tid;
    int n1 = n0 + 128;
    bool v0 = n0 < N_NODES, v1 = n1 < N_NODES;
    int m0 = v0 ? n0 : 0, m1 = v1 ? n1 : 0;

    ull acc0[32], acc1[32];
#pragma unroll
    for (int j = 0; j < 32; j++) {
        ull bb = pack2(sb[2 * j], sb[2 * j + 1]);
        acc0[j] = bb; acc1[j] = bb;
    }
    const float4* A0 = (const float4*)(g_A + m0 * D);
    const float4* A1 = (const float4*)(g_A + m1 * D);
    const float4* X0 = (const float4*)(X + m0 * D);
    const float4* X1 = (const float4*)(X + m1 * D);

    float4 a0 = A0[0], xq0 = X0[0], a1 = A1[0], xq1 = X1[0];

#pragma unroll 1
    for (int kq = 0; kq < 16; kq++) {
        float4 na0, nx0, na1, nx1;
        if (kq < 15) {
            na0 = A0[kq + 1]; nx0 = X0[kq + 1];
            na1 = A1[kq + 1]; nx1 = X1[kq + 1];
        }
        float fa0[4] = {a0.x, a0.y, a0.z, a0.w};
        float fx0[4] = {xq0.x, xq0.y, xq0.z, xq0.w};
        float fa1[4] = {a1.x, a1.y, a1.z, a1.w};
        float fx1[4] = {xq1.x, xq1.y, xq1.z, xq1.w};
#pragma unroll
        for (int kk = 0; kk < 4; kk++) {
            int k = kq * 4 + kk;
            ull pa0 = pack2(fa0[kk], fa0[kk]);
            ull px0 = pack2(fx0[kk], fx0[kk]);
            ull pa1 = pack2(fa1[kk], fa1[kk]);
            ull px1 = pack2(fx1[kk], fx1[kk]);
            const ulonglong2* wlp = (const ulonglong2*)&sWl[k * 64];
            const ulonglong2* wrp = (const ulonglong2*)&sWr[k * 64];
#pragma unroll
            for (int jp = 0; jp < 16; jp++) {
                ulonglong2 wl = wlp[jp];   // LDS.128 broadcast
                ulonglong2 wr = wrp[jp];
                acc0[2 * jp]     = fma2(wl.x, pa0, fma2(wr.x, px0, acc0[2 * jp]));
                acc0[2 * jp + 1] = fma2(wl.y, pa0, fma2(wr.y, px0, acc0[2 * jp + 1]));
                acc1[2 * jp]     = fma2(wl.x, pa1, fma2(wr.x, px1, acc1[2 * jp]));
                acc1[2 * jp + 1] = fma2(wl.y, pa1, fma2(wr.y, px1, acc1[2 * jp + 1]));
            }
        }
        a0 = na0; xq0 = nx0; a1 = na1; xq1 = nx1;
    }

    if (v0) {
        float4* o = (float4*)(out + n0 * D);
#pragma unroll
        for (int q = 0; q < 16; q++) {
            float r0, r1, r2, r3;
            unpack2(acc0[2 * q], r0, r1);
            unpack2(acc0[2 * q + 1], r2, r3);
            if (FIRST) {
                r0 = fmaxf(r0, 0.f); r1 = fmaxf(r1, 0.f);
                r2 = fmaxf(r2, 0.f); r3 = fmaxf(r3, 0.f);
            }
            o[q] = make_float4(r0, r1, r2, r3);
        }
    }
    if (v1) {
        float4* o = (float4*)(out + n1 * D);
#pragma unroll
        for (int q = 0; q < 16; q++) {
            float r0, r1, r2, r3;
            unpack2(acc1[2 * q], r0, r1);
            unpack2(acc1[2 * q + 1], r2, r3);
            if (FIRST) {
                r0 = fmaxf(r0, 0.f); r1 = fmaxf(r1, 0.f);
                r2 = fmaxf(r2, 0.f); r3 = fmaxf(r3, 0.f);
            }
            o[q] = make_float4(r0, r1, r2, r3);
        }
    }
}

extern "C" void kernel_launch(void* const* d_in, const int* in_sizes, int n_in,
                              void* d_out, int out_size) {
    const float* x   = (const float*)d_in[0];
    const void*  ei  = d_in[1];
    const float* W1l = (const float*)d_in[2];
    const float* b1  = (const float*)d_in[3];
    const float* W1r = (const float*)d_in[4];
    const float* W2l = (const float*)d_in[5];
    const float* b2  = (const float*)d_in[6];
    const float* W2r = (const float*)d_in[7];
    float* out = (float*)d_out;

    k_init<<<SCAN_NB, 256>>>((const int*)ei);
    k_convert<<<(N_NODES * D / 4 + 255) / 256, 256>>>(x);
    k_hist<<<(N_EDGES + 255) / 256, 256>>>(ei);
    k_scan1<<<SCAN_NB, 256>>>();
    k_scan23<<<SCAN_NB, 256>>>();
    k_fill<<<(N_EDGES + 255) / 256, 256>>>(ei);

    const int DNB = (N_NODES + 255) / 256;   // 391 blocks of 128 threads

    // Layer 1
    k_agg<true><<<(N_NODES * 32 + 255) / 256, 256>>>();
    k_dense<true><<<DNB, 128>>>(x, W1l, b1, W1r, nullptr);
    k_convertH<<<(N_NODES * D / 4 + 255) / 256, 256>>>();

    // Layer 2
    k_agg<false><<<(N_NODES * 32 + 255) / 256, 256>>>();
    k_dense<false><<<DNB, 128>>>(x, W2l, b2, W2r, out);
}

// round 11
// speedup vs baseline: 1.5257x; 1.0238x over previous
#include <cuda_runtime.h>

#define N_NODES 100000
#define N_EDGES 1600000
#define D 64
#define SCAN_NB 391   // 391*256 = 100096 >= N_NODES

typedef unsigned long long ull;

// Scratch (static __device__ — allocation-free per harness rules)
__device__ int   g_is64;
__device__ int   g_deg[N_NODES];
__device__ int   g_rowoff[N_NODES + 1];
__device__ int   g_cursor[N_NODES];
__device__ float g_dinv[N_NODES];
__device__ int   g_srcidx[N_EDGES];
__device__ int   g_bsum[512];
__device__ float g_A[N_NODES * D];   // aggregated (mean) neighbor feats
__device__ float g_H[N_NODES * D];   // layer-1 hidden

// ---------- packed f32x2 helpers ----------
__device__ __forceinline__ ull fma2(ull a, ull b, ull c) {
    ull d;
    asm("fma.rn.f32x2 %0, %1, %2, %3;" : "=l"(d) : "l"(a), "l"(b), "l"(c));
    return d;
}
__device__ __forceinline__ ull pack2(float x, float y) {
    ull d;
    asm("mov.b64 %0, {%1, %2};" : "=l"(d) : "f"(x), "f"(y));
    return d;
}
__device__ __forceinline__ void unpack2(ull v, float& x, float& y) {
    asm("mov.b64 {%0, %1}, %2;" : "=f"(x), "=f"(y) : "l"(v));
}

__device__ __forceinline__ int clampN(int v) {
    return min(max(v, 0), N_NODES - 1);
}
__device__ __forceinline__ int load_id(const void* ei, long long idx, int is64) {
    int v = is64 ? (int)((const long long*)ei)[idx] : ((const int*)ei)[idx];
    return clampN(v);
}

// ---------- init: zero degrees + dtype detect ----------
__global__ void k_init(const int* __restrict__ ei32) {
    int i = blockIdx.x * blockDim.x + threadIdx.x;
    if (i < N_NODES) g_deg[i] = 0;
    if (i == 0) {
        int odd_zero = 1;
#pragma unroll
        for (int j = 1; j < 64; j += 2)
            if (ei32[j] != 0) odd_zero = 0;
        g_is64 = odd_zero;
    }
}

__global__ void k_hist(const void* __restrict__ ei) {
    int e = blockIdx.x * blockDim.x + threadIdx.x;
    if (e < N_EDGES) {
        int is64 = g_is64;
        int dst = load_id(ei, (long long)N_EDGES + e, is64);
        atomicAdd(&g_deg[dst], 1);
    }
}

__global__ void k_scan1() {
    __shared__ int sh[256];
    int i = blockIdx.x * 256 + threadIdx.x;
    int t = threadIdx.x;
    sh[t] = (i < N_NODES) ? g_deg[i] : 0;
    __syncthreads();
    for (int off = 128; off > 0; off >>= 1) {
        if (t < off) sh[t] += sh[t + off];
        __syncthreads();
    }
    if (t == 0) g_bsum[blockIdx.x] = sh[0];
}

// per-block: redundant scan of 391 block sums + local scan + write CSR arrays
__global__ void k_scan23() {
    __shared__ int sb2[512];
    __shared__ int sh[256];
    int b = blockIdx.x;
    int t = threadIdx.x;
    sb2[t]       = (t < SCAN_NB) ? g_bsum[t] : 0;
    sb2[t + 256] = (t + 256 < SCAN_NB) ? g_bsum[t + 256] : 0;
    __syncthreads();
    for (int off = 1; off < 512; off <<= 1) {
        int v0 = (t >= off) ? sb2[t - off] : 0;
        int v1 = (t + 256 >= off) ? sb2[t + 256 - off] : 0;
        __syncthreads();
        sb2[t] += v0;
        sb2[t + 256] += v1;
        __syncthreads();
    }
    int boff = (b == 0) ? 0 : sb2[b - 1];
    int i = b * 256 + t;
    int d = (i < N_NODES) ? g_deg[i] : 0;
    sh[t] = d;
    __syncthreads();
    for (int off = 1; off < 256; off <<= 1) {
        int v = (t >= off) ? sh[t - off] : 0;
        __syncthreads();
        sh[t] += v;
        __syncthreads();
    }
    if (i < N_NODES) {
        int excl = sh[t] - d + boff;
        g_rowoff[i] = excl;
        g_cursor[i] = excl;
        g_dinv[i] = 1.0f / (float)max(d, 1);
    }
    if (i == 0) g_rowoff[N_NODES] = N_EDGES;
}

__global__ void k_fill(const void* __restrict__ ei) {
    int e = blockIdx.x * blockDim.x + threadIdx.x;
    if (e < N_EDGES) {
        int is64 = g_is64;
        int dst = load_id(ei, (long long)N_EDGES + e, is64);
        int src = load_id(ei, e, is64);
        int pos = atomicAdd(&g_cursor[dst], 1);
        pos = min(max(pos, 0), N_EDGES - 1);
        g_srcidx[pos] = src;
    }
}

// ---------- mean aggregation: warp per node, fp32 gather, no atomics ----------
template <bool FIRST>
__global__ void k_agg(const float* __restrict__ xext) {
    const float* __restrict__ feat = FIRST ? xext : (const float*)g_H;
    int gw = (blockIdx.x * blockDim.x + threadIdx.x) >> 5;
    int lane = threadIdx.x & 31;
    if (gw >= N_NODES) return;
    int s = g_rowoff[gw], e = g_rowoff[gw + 1];
    float ax = 0.f, ay = 0.f;
    int i = s;
    for (; i + 3 < e; i += 4) {   // 4 gathers in flight
        int s0 = g_srcidx[i], s1 = g_srcidx[i + 1];
        int s2 = g_srcidx[i + 2], s3 = g_srcidx[i + 3];
        float2 v0 = *(const float2*)&feat[s0 * D + lane * 2];
        float2 v1 = *(const float2*)&feat[s1 * D + lane * 2];
        float2 v2 = *(const float2*)&feat[s2 * D + lane * 2];
        float2 v3 = *(const float2*)&feat[s3 * D + lane * 2];
        ax += v0.x + v1.x + v2.x + v3.x;
        ay += v0.y + v1.y + v2.y + v3.y;
    }
    for (; i < e; i++) {
        int s0 = g_srcidx[i];
        float2 v = *(const float2*)&feat[s0 * D + lane * 2];
        ax += v.x; ay += v.y;
    }
    float di = g_dinv[gw];
    *(float2*)&g_A[gw * D + lane * 2] = make_float2(ax * di, ay * di);
}

// ---------- fused dual-linear: out = A@Wl^T + b + X@Wr^T (+relu) ----------
// 128 threads: tid>>6 = output half (32 outs), tid&63 = node column.
// 4 nodes/thread (block = 256 nodes). Per k-step per warp: 16 LDS.128 vs
// 128 FFMA2 (1:8) — smem crossbar and FMA pipe balanced.
template <bool FIRST>
__global__ void __launch_bounds__(128)
k_dense(const float* __restrict__ xext,
        const float* __restrict__ Wl, const float* __restrict__ bias,
        const float* __restrict__ Wr, float* __restrict__ outext) {
    __shared__ float sWl[64 * 64];
    __shared__ float sWr[64 * 64];
    __shared__ float sb[64];
    const float* __restrict__ X = FIRST ? xext : (const float*)g_H;
    float* out = FIRST ? (float*)g_H : outext;
    int tid = threadIdx.x;
    for (int i = tid; i < 4096; i += 128) {
        int j = i >> 6, k = i & 63;
        sWl[k * 64 + j] = Wl[i];   // sW[k][j] = W[j][k]
        sWr[k * 64 + j] = Wr[i];
    }
    if (tid < 64) sb[tid] = bias[tid];
    __syncthreads();

    int half = tid >> 6;          // 0/1: which 32 outputs (uniform per warp)
    int col  = tid & 63;
    int base = blockIdx.x * 256 + col;

    int n[4], m[4]; bool v[4];
#pragma unroll
    for (int i = 0; i < 4; i++) {
        n[i] = base + i * 64;
        v[i] = n[i] < N_NODES;
        m[i] = v[i] ? n[i] : 0;
    }

    ull acc[4][16];
#pragma unroll
    for (int j = 0; j < 16; j++) {
        ull bb = pack2(sb[half * 32 + 2 * j], sb[half * 32 + 2 * j + 1]);
#pragma unroll
        for (int i = 0; i < 4; i++) acc[i][j] = bb;
    }

    const float4* Aq[4];
    const float4* Xq[4];
#pragma unroll
    for (int i = 0; i < 4; i++) {
        Aq[i] = (const float4*)(g_A + m[i] * D);
        Xq[i] = (const float4*)(X + m[i] * D);
    }

#pragma unroll 1
    for (int kq = 0; kq < 16; kq++) {
        float fa[4][4], fx[4][4];
#pragma unroll
        for (int i = 0; i < 4; i++) {
            float4 a = Aq[i][kq], xv = Xq[i][kq];
            fa[i][0] = a.x;  fa[i][1] = a.y;  fa[i][2] = a.z;  fa[i][3] = a.w;
            fx[i][0] = xv.x; fx[i][1] = xv.y; fx[i][2] = xv.z; fx[i][3] = xv.w;
        }
#pragma unroll
        for (int kk = 0; kk < 4; kk++) {
            int k = kq * 4 + kk;
            ull pa[4], px[4];
#pragma unroll
            for (int i = 0; i < 4; i++) {
                pa[i] = pack2(fa[i][kk], fa[i][kk]);
                px[i] = pack2(fx[i][kk], fx[i][kk]);
            }
            const ulonglong2* wlp = (const ulonglong2*)&sWl[k * 64 + half * 32];
            const ulonglong2* wrp = (const ulonglong2*)&sWr[k * 64 + half * 32];
#pragma unroll
            for (int jp = 0; jp < 8; jp++) {
                ulonglong2 wl = wlp[jp];   // LDS.128 broadcast (warp-uniform)
                ulonglong2 wr = wrp[jp];
#pragma unroll
                for (int i = 0; i < 4; i++) {
                    acc[i][2 * jp]     = fma2(wl.x, pa[i], fma2(wr.x, px[i], acc[i][2 * jp]));
                    acc[i][2 * jp + 1] = fma2(wl.y, pa[i], fma2(wr.y, px[i], acc[i][2 * jp + 1]));
                }
            }
        }
    }

#pragma unroll
    for (int i = 0; i < 4; i++) {
        if (!v[i]) continue;
        float4* o = (float4*)(out + n[i] * D + half * 32);
#pragma unroll
        for (int q = 0; q < 8; q++) {
            float r0, r1, r2, r3;
            unpack2(acc[i][2 * q], r0, r1);
            unpack2(acc[i][2 * q + 1], r2, r3);
            if (FIRST) {
                r0 = fmaxf(r0, 0.f); r1 = fmaxf(r1, 0.f);
                r2 = fmaxf(r2, 0.f); r3 = fmaxf(r3, 0.f);
            }
            o[q] = make_float4(r0, r1, r2, r3);
        }
    }
}

extern "C" void kernel_launch(void* const* d_in, const int* in_sizes, int n_in,
                              void* d_out, int out_size) {
    const float* x   = (const float*)d_in[0];
    const void*  ei  = d_in[1];
    const float* W1l = (const float*)d_in[2];
    const float* b1  = (const float*)d_in[3];
    const float* W1r = (const float*)d_in[4];
    const float* W2l = (const float*)d_in[5];
    const float* b2  = (const float*)d_in[6];
    const float* W2r = (const float*)d_in[7];
    float* out = (float*)d_out;

    k_init<<<SCAN_NB, 256>>>((const int*)ei);
    k_hist<<<(N_EDGES + 255) / 256, 256>>>(ei);
    k_scan1<<<SCAN_NB, 256>>>();
    k_scan23<<<SCAN_NB, 256>>>();
    k_fill<<<(N_EDGES + 255) / 256, 256>>>(ei);

    const int DNB = (N_NODES + 255) / 256;   // 391 blocks, 256 nodes each

    // Layer 1
    k_agg<true><<<(N_NODES * 32 + 255) / 256, 256>>>(x);
    k_dense<true><<<DNB, 128>>>(x, W1l, b1, W1r, nullptr);

    // Layer 2
    k_agg<false><<<(N_NODES * 32 + 255) / 256, 256>>>(x);
    k_dense<false><<<DNB, 128>>>(x, W2l, b2, W2r, out);
}

// round 13
// speedup vs baseline: 1.5930x; 1.0441x over previous
#include <cuda_runtime.h>
#include <mma.h>
#include <cstdint>

#define N_NODES 100000
#define N_EDGES 1600000
#define D 64
#define SCAN_NB 391   // 391*256 = 100096 >= N_NODES
#define NTILES 782    // 782*128 = 100096 >= N_NODES
#define ULD 132       // padded leading dim for U / B tiles (floats)
#define OLD 68        // padded leading dim for output staging

using namespace nvcuda;

// Scratch (static __device__ — allocation-free per harness rules)
__device__ int   g_is64;
__device__ int   g_deg[N_NODES];
__device__ int   g_rowoff[N_NODES + 1];
__device__ int   g_cursor[N_NODES];
__device__ float g_dinv[N_NODES];
__device__ int   g_srcidx[N_EDGES];
__device__ int   g_bsum[512];
__device__ float g_A[N_NODES * D];   // aggregated (mean) neighbor feats
__device__ float g_H[N_NODES * D];   // layer-1 hidden

__device__ __forceinline__ int clampN(int v) {
    return min(max(v, 0), N_NODES - 1);
}
__device__ __forceinline__ int load_id(const void* ei, long long idx, int is64) {
    int v = is64 ? (int)((const long long*)ei)[idx] : ((const int*)ei)[idx];
    return clampN(v);
}

// ---------- init: zero degrees + dtype detect ----------
__global__ void k_init(const int* __restrict__ ei32) {
    int i = blockIdx.x * blockDim.x + threadIdx.x;
    if (i < N_NODES) g_deg[i] = 0;
    if (i == 0) {
        int odd_zero = 1;
#pragma unroll
        for (int j = 1; j < 64; j += 2)
            if (ei32[j] != 0) odd_zero = 0;
        g_is64 = odd_zero;
    }
}

__global__ void k_hist(const void* __restrict__ ei) {
    int e = blockIdx.x * blockDim.x + threadIdx.x;
    if (e < N_EDGES) {
        int is64 = g_is64;
        int dst = load_id(ei, (long long)N_EDGES + e, is64);
        atomicAdd(&g_deg[dst], 1);
    }
}

__global__ void k_scan1() {
    __shared__ int sh[256];
    int i = blockIdx.x * 256 + threadIdx.x;
    int t = threadIdx.x;
    sh[t] = (i < N_NODES) ? g_deg[i] : 0;
    __syncthreads();
    for (int off = 128; off > 0; off >>= 1) {
        if (t < off) sh[t] += sh[t + off];
        __syncthreads();
    }
    if (t == 0) g_bsum[blockIdx.x] = sh[0];
}

__global__ void k_scan23() {
    __shared__ int sb2[512];
    __shared__ int sh[256];
    int b = blockIdx.x;
    int t = threadIdx.x;
    sb2[t]       = (t < SCAN_NB) ? g_bsum[t] : 0;
    sb2[t + 256] = (t + 256 < SCAN_NB) ? g_bsum[t + 256] : 0;
    __syncthreads();
    for (int off = 1; off < 512; off <<= 1) {
        int v0 = (t >= off) ? sb2[t - off] : 0;
        int v1 = (t + 256 >= off) ? sb2[t + 256 - off] : 0;
        __syncthreads();
        sb2[t] += v0;
        sb2[t + 256] += v1;
        __syncthreads();
    }
    int boff = (b == 0) ? 0 : sb2[b - 1];
    int i = b * 256 + t;
    int d = (i < N_NODES) ? g_deg[i] : 0;
    sh[t] = d;
    __syncthreads();
    for (int off = 1; off < 256; off <<= 1) {
        int v = (t >= off) ? sh[t - off] : 0;
        __syncthreads();
        sh[t] += v;
        __syncthreads();
    }
    if (i < N_NODES) {
        int excl = sh[t] - d + boff;
        g_rowoff[i] = excl;
        g_cursor[i] = excl;
        g_dinv[i] = 1.0f / (float)max(d, 1);
    }
    if (i == 0) g_rowoff[N_NODES] = N_EDGES;
}

__global__ void k_fill(const void* __restrict__ ei) {
    int e = blockIdx.x * blockDim.x + threadIdx.x;
    if (e < N_EDGES) {
        int is64 = g_is64;
        int dst = load_id(ei, (long long)N_EDGES + e, is64);
        int src = load_id(ei, e, is64);
        int pos = atomicAdd(&g_cursor[dst], 1);
        pos = min(max(pos, 0), N_EDGES - 1);
        g_srcidx[pos] = src;
    }
}

// ---------- mean aggregation: warp per node, fp32 gather, no atomics ----------
template <bool FIRST>
__global__ void k_agg(const float* __restrict__ xext) {
    const float* __restrict__ feat = FIRST ? xext : (const float*)g_H;
    int gw = (blockIdx.x * blockDim.x + threadIdx.x) >> 5;
    int lane = threadIdx.x & 31;
    if (gw >= N_NODES) return;
    int s = g_rowoff[gw], e = g_rowoff[gw + 1];
    float ax = 0.f, ay = 0.f;
    int i = s;
    for (; i + 3 < e; i += 4) {
        int s0 = g_srcidx[i], s1 = g_srcidx[i + 1];
        int s2 = g_srcidx[i + 2], s3 = g_srcidx[i + 3];
        float2 v0 = *(const float2*)&feat[s0 * D + lane * 2];
        float2 v1 = *(const float2*)&feat[s1 * D + lane * 2];
        float2 v2 = *(const float2*)&feat[s2 * D + lane * 2];
        float2 v3 = *(const float2*)&feat[s3 * D + lane * 2];
        ax += v0.x + v1.x + v2.x + v3.x;
        ay += v0.y + v1.y + v2.y + v3.y;
    }
    for (; i < e; i++) {
        int s0 = g_srcidx[i];
        float2 v = *(const float2*)&feat[s0 * D + lane * 2];
        ax += v.x; ay += v.y;
    }
    float di = g_dinv[gw];
    *(float2*)&g_A[gw * D + lane * 2] = make_float2(ax * di, ay * di);
}

// ---------- wmma tf32 dense: out = [A|X] @ [Wl|Wr]^T + b (+relu) ----------
// dyn smem: sU[128*ULD] (also reused as output staging) | sB[64*ULD]
#define DSM_TOTAL ((128 * ULD + 64 * ULD) * 4)

template <bool FIRST>
__global__ void __launch_bounds__(128)
k_denseT(const float* __restrict__ xext,
         const float* __restrict__ Wl, const float* __restrict__ bias,
         const float* __restrict__ Wr, float* __restrict__ outext) {
    extern __shared__ float dsm[];
    float* sU = dsm;                  // [128][ULD] tf32 (row-major)
    float* sB = dsm + 128 * ULD;      // [64][ULD]  Wc[n][k] (col-major B: k fast)
    __shared__ float s_bias[64];

    const float* __restrict__ X = FIRST ? xext : (const float*)g_H;
    float* out = FIRST ? (float*)g_H : outext;

    int tid = threadIdx.x;
    int wid = tid >> 5;
    if (tid < 64) s_bias[tid] = bias[tid];

    // fill U row tid: k<64 from A, k>=64 from X (converted to tf32 bits)
    int node = clampN(blockIdx.x * 128 + tid);
    {
        const float4* Ar = (const float4*)(g_A + node * D);
        const float4* Xr = (const float4*)(X + node * D);
        float* ur = sU + tid * ULD;
#pragma unroll
        for (int q = 0; q < 16; q++) {
            float4 v = Ar[q];
            ur[4 * q]     = wmma::__float_to_tf32(v.x);
            ur[4 * q + 1] = wmma::__float_to_tf32(v.y);
            ur[4 * q + 2] = wmma::__float_to_tf32(v.z);
            ur[4 * q + 3] = wmma::__float_to_tf32(v.w);
        }
#pragma unroll
        for (int q = 0; q < 16; q++) {
            float4 v = Xr[q];
            ur[64 + 4 * q]     = wmma::__float_to_tf32(v.x);
            ur[64 + 4 * q + 1] = wmma::__float_to_tf32(v.y);
            ur[64 + 4 * q + 2] = wmma::__float_to_tf32(v.z);
            ur[64 + 4 * q + 3] = wmma::__float_to_tf32(v.w);
        }
    }
    // fill B: sB[n][k], n<64, k<128; k<64 -> Wl[n][k], else Wr[n][k-64]
    for (int idx = tid; idx < 64 * 128; idx += 128) {
        int n = idx >> 7, k = idx & 127;
        float w = (k < 64) ? Wl[n * 64 + k] : Wr[n * 64 + (k - 64)];
        sB[n * ULD + k] = wmma::__float_to_tf32(w);
    }
    __syncthreads();

    // warp wid: rows [wid*32, wid*32+32), all 64 cols
    wmma::fragment<wmma::accumulator, 16, 16, 8, float> acc[2][4];
#pragma unroll
    for (int mt = 0; mt < 2; mt++)
#pragma unroll
        for (int nt = 0; nt < 4; nt++)
            wmma::fill_fragment(acc[mt][nt], 0.0f);

    int m0 = wid * 32;
#pragma unroll 1
    for (int k = 0; k < 128; k += 8) {
        wmma::fragment<wmma::matrix_b, 16, 16, 8, wmma::precision::tf32,
                       wmma::col_major> fb[4];
#pragma unroll
        for (int nt = 0; nt < 4; nt++)
            wmma::load_matrix_sync(fb[nt], sB + (nt * 16) * ULD + k, ULD);
#pragma unroll
        for (int mt = 0; mt < 2; mt++) {
            wmma::fragment<wmma::matrix_a, 16, 16, 8, wmma::precision::tf32,
                           wmma::row_major> fa;
            wmma::load_matrix_sync(fa, sU + (m0 + mt * 16) * ULD + k, ULD);
#pragma unroll
            for (int nt = 0; nt < 4; nt++)
                wmma::mma_sync(acc[mt][nt], fa, fb[nt], acc[mt][nt]);
        }
    }

    __syncthreads();   // all warps done reading sU; reuse as output staging
    float* sO = sU;    // [128][OLD]
#pragma unroll
    for (int mt = 0; mt < 2; mt++)
#pragma unroll
        for (int nt = 0; nt < 4; nt++)
            wmma::store_matrix_sync(sO + (m0 + mt * 16) * OLD + nt * 16,
                                    acc[mt][nt], OLD, wmma::mem_row_major);
    __syncthreads();

    // epilogue: thread tid -> node row
    int onode = blockIdx.x * 128 + tid;
    if (onode < N_NODES) {
        const float* r = sO + tid * OLD;
        float4* o = (float4*)(out + onode * D);
#pragma unroll
        for (int q = 0; q < 16; q++) {
            float r0 = r[4 * q]     + s_bias[4 * q];
            float r1 = r[4 * q + 1] + s_bias[4 * q + 1];
            float r2 = r[4 * q + 2] + s_bias[4 * q + 2];
            float r3 = r[4 * q + 3] + s_bias[4 * q + 3];
            if (FIRST) {
                r0 = fmaxf(r0, 0.f); r1 = fmaxf(r1, 0.f);
                r2 = fmaxf(r2, 0.f); r3 = fmaxf(r3, 0.f);
            }
            o[q] = make_float4(r0, r1, r2, r3);
        }
    }
}

extern "C" void kernel_launch(void* const* d_in, const int* in_sizes, int n_in,
                              void* d_out, int out_size) {
    const float* x   = (const float*)d_in[0];
    const void*  ei  = d_in[1];
    const float* W1l = (const float*)d_in[2];
    const float* b1  = (const float*)d_in[3];
    const float* W1r = (const float*)d_in[4];
    const float* W2l = (const float*)d_in[5];
    const float* b2  = (const float*)d_in[6];
    const float* W2r = (const float*)d_in[7];
    float* out = (float*)d_out;

    static int s_attr = 0;
    if (!s_attr) {
        cudaFuncSetAttribute(k_denseT<true>,
            cudaFuncAttributeMaxDynamicSharedMemorySize, DSM_TOTAL);
        cudaFuncSetAttribute(k_denseT<false>,
            cudaFuncAttributeMaxDynamicSharedMemorySize, DSM_TOTAL);
        s_attr = 1;
    }

    k_init<<<SCAN_NB, 256>>>((const int*)ei);
    k_hist<<<(N_EDGES + 255) / 256, 256>>>(ei);
    k_scan1<<<SCAN_NB, 256>>>();
    k_scan23<<<SCAN_NB, 256>>>();
    k_fill<<<(N_EDGES + 255) / 256, 256>>>(ei);

    // Layer 1
    k_agg<true><<<(N_NODES * 32 + 255) / 256, 256>>>(x);
    k_denseT<true><<<NTILES, 128, DSM_TOTAL>>>(x, W1l, b1, W1r, nullptr);

    // Layer 2
    k_agg<false><<<(N_NODES * 32 + 255) / 256, 256>>>(x);
    k_denseT<false><<<NTILES, 128, DSM_TOTAL>>>(x, W2l, b2, W2r, out);
}